// round 4
// baseline (speedup 1.0000x reference)
#include <cuda_runtime.h>
#include <cuda_bf16.h>
#include <stdint.h>

#define CDIM 256
#define HW_  9216
#define TT   32
#define VV   256
#define MTOT 8192
#define BM   128
#define BN   128
#define KPAD 264            // 256 + 8 bf16 pad -> conflict-free LDS
#define SMEM_BYTES ((BM + BN) * KPAD * 2)

__device__ __nv_bfloat16 g_feats[(size_t)MTOT * CDIM];
__device__ float g_neg_sum[MTOT];
__device__ float g_pos_sum[MTOT];

// ---------------------------------------------------------------------------
// K1: gather + L2 normalize (fp32) -> bf16 feats; also zero accumulators.
// grid (4, 32): blockIdx.y = t, blockIdx.x = quarter of v. 256 thr = (cg, vl).
// ---------------------------------------------------------------------------
__global__ void k_gather(const float* __restrict__ features,
                         const int* __restrict__ batch_inds,
                         const int* __restrict__ si32) {
    const int tid = threadIdx.x;
    const int t  = blockIdx.y;
    const int vq = blockIdx.x;
    const int vl = tid & 63;
    const int cg = tid >> 6;
    const int v  = vq * 64 + vl;

    // zero row accumulators (32768 threads cover 8192 rows)
    int gz = ((blockIdx.y * 4 + blockIdx.x) << 8) + tid;
    if (gz < MTOT) { g_neg_sum[gz] = 0.f; g_pos_sum[gz] = 0.f; }

    // sample_inds may arrive as int64 or int32 (JAX x64 flag); sniff high words.
    bool is64 = (si32[1] == 0) && (si32[3] == 0) && (si32[5] == 0) && (si32[7] == 0);
    const int idx = t * VV + v;
    const int s = is64 ? (int)((const long long*)si32)[idx] : si32[idx];
    const int b = batch_inds[t];
    const float* base = features + (size_t)b * CDIM * HW_ + s;

    float partial = 0.f;
#pragma unroll 8
    for (int c = cg * 64; c < cg * 64 + 64; c++) {
        float x = __ldg(&base[(size_t)c * HW_]);
        partial += x * x;
    }
    __shared__ float red[4][64];
    __shared__ float s_inv[64];
    red[cg][vl] = partial;
    __syncthreads();
    if (cg == 0) {
        float ss = red[0][vl] + red[1][vl] + red[2][vl] + red[3][vl];
        float nrm = fmaxf(sqrtf(ss), 1e-12f);
        s_inv[vl] = 1.0f / nrm;
    }
    __syncthreads();
    const float inv = s_inv[vl];
    __nv_bfloat16* dst = g_feats + (size_t)(t * VV + v) * CDIM;
#pragma unroll 8
    for (int c = cg * 64; c < cg * 64 + 64; c += 2) {
        float x0 = __ldg(&base[(size_t)c * HW_]) * inv;
        float x1 = __ldg(&base[(size_t)(c + 1) * HW_]) * inv;
        __nv_bfloat162 p;
        p.x = __float2bfloat16(x0);
        p.y = __float2bfloat16(x1);
        *(__nv_bfloat162*)&dst[c] = p;
    }
}

// ---------------------------------------------------------------------------
// mma.sync m16n8k16 bf16 (A row-major, B col-major i.e. [n][k] storage)
// ---------------------------------------------------------------------------
__device__ __forceinline__ void mma_bf16(float c[4], const uint32_t a[4],
                                         const uint32_t b[2]) {
    asm volatile(
        "mma.sync.aligned.m16n8k16.row.col.f32.bf16.bf16.f32 "
        "{%0,%1,%2,%3}, {%4,%5,%6,%7}, {%8,%9}, {%0,%1,%2,%3};\n"
        : "+f"(c[0]), "+f"(c[1]), "+f"(c[2]), "+f"(c[3])
        : "r"(a[0]), "r"(a[1]), "r"(a[2]), "r"(a[3]), "r"(b[0]), "r"(b[1]));
}

// ---------------------------------------------------------------------------
// K2/K3: one 128-row block x 16 j-tiles per CTA. grid (4, 64).
// POSPASS=false: neg_sum[i] = sum_{lab!=} exp(2d-2)
// POSPASS=true : pos_sum[i] = sum_{lab==, j!=i} [ l - log(exp(l)+neg_sum_i) ]
// (fixed stabilizer m=2 cancels analytically vs. the reference's row max)
// ---------------------------------------------------------------------------
template <bool POSPASS>
__global__ void k_pass(const int* __restrict__ labels) {
    extern __shared__ __nv_bfloat16 smem[];
    __nv_bfloat16* As = smem;                 // [BM][KPAD]
    __nv_bfloat16* Bs = smem + BM * KPAD;     // [BN][KPAD]

    const int rb = blockIdx.y;                // 0..63 row block
    const int jc = blockIdx.x;                // 0..3  j chunk
    const int rowBase = rb * BM;
    const int myLab = labels[rb >> 1];        // 128 rows lie in one t
    const int tid = threadIdx.x;
    const int lane = tid & 31, warp = tid >> 5;
    const int wm = warp >> 1, wn = warp & 1;  // 4 (m) x 2 (n) warps
    const int g = lane >> 2, tig = lane & 3;

    if (POSPASS) {
        bool any = false;
        for (int jt = jc * 16; jt < jc * 16 + 16; jt++)
            any |= (labels[jt >> 1] == myLab);
        if (!any) return;                     // uniform
    }

    // load A tile (rows rowBase..+127, full K) into padded shared
    {
        const uint4* src = (const uint4*)g_feats + (size_t)rowBase * (CDIM / 8);
#pragma unroll
        for (int it = 0; it < (BM * CDIM / 8) / 256; it++) {
            int i = it * 256 + tid;
            int r = i >> 5, c = i & 31;
            *(uint4*)&As[r * KPAD + c * 8] = src[r * 32 + c];
        }
    }

    float rowacc[4] = {0.f, 0.f, 0.f, 0.f};
    float nsum_row[4];
    if (POSPASS) {
#pragma unroll
        for (int k = 0; k < 4; k++) {
            int r = rowBase + wm * 32 + (k >> 1) * 16 + (k & 1) * 8 + g;
            nsum_row[k] = g_neg_sum[r];
        }
    }

    for (int jt = jc * 16; jt < jc * 16 + 16; jt++) {
        bool same = (labels[jt >> 1] == myLab);
        if (POSPASS ? (!same) : same) continue;   // uniform branch
        __syncthreads();                          // Bs free from prev iter
        {
            const uint4* src = (const uint4*)g_feats + (size_t)jt * BN * (CDIM / 8);
#pragma unroll
            for (int it = 0; it < (BN * CDIM / 8) / 256; it++) {
                int i = it * 256 + tid;
                int r = i >> 5, c = i & 31;
                *(uint4*)&Bs[r * KPAD + c * 8] = src[r * 32 + c];
            }
        }
        __syncthreads();

        float acc[2][8][4];
#pragma unroll
        for (int mi = 0; mi < 2; mi++)
#pragma unroll
            for (int ni = 0; ni < 8; ni++)
#pragma unroll
                for (int e = 0; e < 4; e++) acc[mi][ni][e] = 0.f;

#pragma unroll 4
        for (int kk = 0; kk < CDIM; kk += 16) {
            uint32_t a[2][4], b[8][2];
#pragma unroll
            for (int mi = 0; mi < 2; mi++) {
                const __nv_bfloat16* ap =
                    &As[(wm * 32 + mi * 16 + g) * KPAD + kk + tig * 2];
                a[mi][0] = *(const uint32_t*)ap;
                a[mi][1] = *(const uint32_t*)(ap + 8 * KPAD);
                a[mi][2] = *(const uint32_t*)(ap + 8);
                a[mi][3] = *(const uint32_t*)(ap + 8 * KPAD + 8);
            }
#pragma unroll
            for (int ni = 0; ni < 8; ni++) {
                const __nv_bfloat16* bp =
                    &Bs[(wn * 64 + ni * 8 + g) * KPAD + kk + tig * 2];
                b[ni][0] = *(const uint32_t*)bp;
                b[ni][1] = *(const uint32_t*)(bp + 8);
            }
#pragma unroll
            for (int mi = 0; mi < 2; mi++)
#pragma unroll
                for (int ni = 0; ni < 8; ni++)
                    mma_bf16(acc[mi][ni], a[mi], b[ni]);
        }

        const int jBase = jt * BN;
#pragma unroll
        for (int mi = 0; mi < 2; mi++) {
#pragma unroll
            for (int h = 0; h < 2; h++) {
                const int ridx = mi * 2 + h;
                const int gi = rowBase + wm * 32 + mi * 16 + h * 8 + g;
                float sum = 0.f;
#pragma unroll
                for (int ni = 0; ni < 8; ni++) {
#pragma unroll
                    for (int e = 0; e < 2; e++) {
                        float d = acc[mi][ni][h * 2 + e];
                        float l = 2.f * d - 2.f;   // /TEMPERATURE, minus m=2
                        if (POSPASS) {
                            int gj = jBase + wn * 64 + ni * 8 + tig * 2 + e;
                            if (gi != gj)
                                sum += l - __logf(__expf(l) + nsum_row[ridx]);
                        } else {
                            sum += __expf(l);
                        }
                    }
                }
                rowacc[ridx] += sum;
            }
        }
    }

    // quad-shuffle reduce (lanes sharing a row differ only in tig), then atomic
#pragma unroll
    for (int k = 0; k < 4; k++) {
        float v = rowacc[k];
        v += __shfl_xor_sync(0xffffffffu, v, 1);
        v += __shfl_xor_sync(0xffffffffu, v, 2);
        if (tig == 0) {
            int r = rowBase + wm * 32 + (k >> 1) * 16 + (k & 1) * 8 + g;
            atomicAdd(POSPASS ? &g_pos_sum[r] : &g_neg_sum[r], v);
        }
    }
}

// ---------------------------------------------------------------------------
// K4: loss = -mean_i( pos_sum[i] / (V * same_label_count(t_i) - 1) )
// ---------------------------------------------------------------------------
__global__ void k_final(const int* __restrict__ labels, float* __restrict__ out) {
    __shared__ float red[256];
    __shared__ float s_cnt[TT];
    const int tid = threadIdx.x;
    if (tid < TT) {
        int ml = labels[tid], c = 0;
        for (int u = 0; u < TT; u++) c += (labels[u] == ml) ? 1 : 0;
        s_cnt[tid] = (float)(c * VV - 1);   // always >= 255 > EPS
    }
    __syncthreads();
    float s = 0.f;
    for (int i = tid; i < MTOT; i += 256)
        s += g_pos_sum[i] / s_cnt[i >> 8];
    red[tid] = s;
    __syncthreads();
    for (int off = 128; off > 0; off >>= 1) {
        if (tid < off) red[tid] += red[tid + off];
        __syncthreads();
    }
    if (tid == 0) out[0] = -red[0] / (float)MTOT;
}

// ---------------------------------------------------------------------------
extern "C" void kernel_launch(void* const* d_in, const int* in_sizes, int n_in,
                              void* d_out, int out_size) {
    const float* features   = (const float*)d_in[0];
    const int*   batch_inds = (const int*)d_in[1];
    const int*   si32       = (const int*)d_in[2];  // int32 or int64 (sniffed)
    const int*   labels     = (const int*)d_in[3];
    float*       out        = (float*)d_out;

    cudaFuncSetAttribute(k_pass<false>,
                         cudaFuncAttributeMaxDynamicSharedMemorySize, SMEM_BYTES);
    cudaFuncSetAttribute(k_pass<true>,
                         cudaFuncAttributeMaxDynamicSharedMemorySize, SMEM_BYTES);

    k_gather<<<dim3(4, TT), 256>>>(features, batch_inds, si32);
    k_pass<false><<<dim3(4, 64), 256, SMEM_BYTES>>>(labels);
    k_pass<true ><<<dim3(4, 64), 256, SMEM_BYTES>>>(labels);
    k_final<<<1, 256>>>(labels, out);
}

// round 5
// speedup vs baseline: 1.0781x; 1.0781x over previous
#include <cuda_runtime.h>
#include <cuda_bf16.h>
#include <cuda_fp16.h>
#include <stdint.h>

#define CDIM 256
#define HW_  9216
#define TT   32
#define VV   256
#define MTOT 8192
#define BM   128
#define BN   128
#define KPAD 264            // 256 + 8 bf16 pad -> conflict-free LDS
// smem: A tile + double-buffered B tile
#define SMEM_BYTES ((BM + 2 * BN) * KPAD * 2)

__device__ __align__(256) __nv_bfloat16 g_feats[(size_t)MTOT * CDIM];
__device__ float g_neg_sum[MTOT];
__device__ float g_pos_sum[MTOT];

// ---------------------------------------------------------------------------
// K1: gather + L2 normalize (fp32) -> bf16 feats; zero accumulators + out.
// grid (4, 32): blockIdx.y = t, blockIdx.x = quarter of v. 256 thr = (cg, vl).
// ---------------------------------------------------------------------------
__global__ void k_gather(const float* __restrict__ features,
                         const int* __restrict__ batch_inds,
                         const int* __restrict__ si32,
                         float* __restrict__ out) {
    const int tid = threadIdx.x;
    const int t  = blockIdx.y;
    const int vq = blockIdx.x;
    const int vl = tid & 63;
    const int cg = tid >> 6;
    const int v  = vq * 64 + vl;

    if (blockIdx.x == 0 && blockIdx.y == 0 && tid == 0) out[0] = 0.f;

    // zero row accumulators (32768 threads cover 8192 rows)
    int gz = ((blockIdx.y * 4 + blockIdx.x) << 8) + tid;
    if (gz < MTOT) { g_neg_sum[gz] = 0.f; g_pos_sum[gz] = 0.f; }

    // sample_inds may arrive as int64 or int32 (JAX x64 flag); sniff high words.
    bool is64 = (si32[1] == 0) && (si32[3] == 0) && (si32[5] == 0) && (si32[7] == 0);
    const int idx = t * VV + v;
    const int s = is64 ? (int)((const long long*)si32)[idx] : si32[idx];
    const int b = batch_inds[t];
    const float* base = features + (size_t)b * CDIM * HW_ + s;

    float partial = 0.f;
#pragma unroll 8
    for (int c = cg * 64; c < cg * 64 + 64; c++) {
        float x = __ldg(&base[(size_t)c * HW_]);
        partial += x * x;
    }
    __shared__ float red[4][64];
    __shared__ float s_inv[64];
    red[cg][vl] = partial;
    __syncthreads();
    if (cg == 0) {
        float ss = red[0][vl] + red[1][vl] + red[2][vl] + red[3][vl];
        float nrm = fmaxf(sqrtf(ss), 1e-12f);
        s_inv[vl] = 1.0f / nrm;
    }
    __syncthreads();
    const float inv = s_inv[vl];
    __nv_bfloat16* dst = g_feats + (size_t)(t * VV + v) * CDIM;
#pragma unroll 8
    for (int c = cg * 64; c < cg * 64 + 64; c += 2) {
        float x0 = __ldg(&base[(size_t)c * HW_]) * inv;
        float x1 = __ldg(&base[(size_t)(c + 1) * HW_]) * inv;
        __nv_bfloat162 p;
        p.x = __float2bfloat16(x0);
        p.y = __float2bfloat16(x1);
        *(__nv_bfloat162*)&dst[c] = p;
    }
}

// ---------------------------------------------------------------------------
// mma.sync m16n8k16 bf16 (A row-major, B col-major i.e. [n][k] storage)
// ---------------------------------------------------------------------------
__device__ __forceinline__ void mma_bf16(float c[4], const uint32_t a[4],
                                         const uint32_t b[2]) {
    asm volatile(
        "mma.sync.aligned.m16n8k16.row.col.f32.bf16.bf16.f32 "
        "{%0,%1,%2,%3}, {%4,%5,%6,%7}, {%8,%9}, {%0,%1,%2,%3};\n"
        : "+f"(c[0]), "+f"(c[1]), "+f"(c[2]), "+f"(c[3])
        : "r"(a[0]), "r"(a[1]), "r"(a[2]), "r"(a[3]), "r"(b[0]), "r"(b[1]));
}

__device__ __forceinline__ void cp16(uint32_t smem_dst, const void* gsrc) {
    asm volatile("cp.async.cg.shared.global [%0], [%1], 16;\n"
                 :: "r"(smem_dst), "l"(gsrc));
}

// issue async load of a full 128x256 bf16 B tile (16 cp.async per thread)
__device__ __forceinline__ void issue_B(uint32_t bs_addr, int jt, int tid) {
    const uint4* src = (const uint4*)g_feats + (size_t)jt * BN * (CDIM / 8);
#pragma unroll
    for (int it = 0; it < (BN * CDIM / 8) / 256; it++) {
        int i = it * 256 + tid;
        int r = i >> 5, c = i & 31;
        cp16(bs_addr + r * (KPAD * 2) + c * 16, src + r * 32 + c);
    }
    asm volatile("cp.async.commit_group;\n");
}

// ---------------------------------------------------------------------------
// K2/K3: one 128-row block x NJT j-tiles per CTA.
// POSPASS=false (grid 2x64): neg_sum[i] = sum_{lab!=} exp(2d-2)   [f16x2 ex2]
// POSPASS=true  (grid 4x64): pos_sum[i] = sum_{lab==, j!=i} [ l - log(e^l + ns_i) ]
// (fixed stabilizer m=2 cancels analytically vs. the reference's row max)
// ---------------------------------------------------------------------------
template <bool POSPASS, int NJT>
__global__ void k_pass(const int* __restrict__ labels) {
    extern __shared__ __nv_bfloat16 smem[];
    __nv_bfloat16* As = smem;                       // [BM][KPAD]
    __nv_bfloat16* Bs0 = smem + BM * KPAD;          // two [BN][KPAD] buffers

    const int rb = blockIdx.y;
    const int jc = blockIdx.x;
    const int rowBase = rb * BM;
    const int myLab = labels[rb >> 1];              // 128 rows lie in one t
    const int tid = threadIdx.x;
    const int lane = tid & 31, warp = tid >> 5;
    const int wm = warp >> 1, wn = warp & 1;        // 4(m) x 2(n) warps
    const int g = lane >> 2, tig = lane & 3;

    const int jEnd = jc * NJT + NJT;
    // first wanted tile (uniform across threads)
    int cur = jc * NJT;
    while (cur < jEnd && ((labels[cur >> 1] == myLab) != POSPASS)) cur++;
    if (cur >= jEnd) return;

    // load A tile (rows rowBase..+127, full K) into padded shared
    {
        const uint4* src = (const uint4*)g_feats + (size_t)rowBase * (CDIM / 8);
#pragma unroll
        for (int it = 0; it < (BM * CDIM / 8) / 256; it++) {
            int i = it * 256 + tid;
            int r = i >> 5, c = i & 31;
            *(uint4*)&As[r * KPAD + c * 8] = src[r * 32 + c];
        }
    }

    uint32_t bs_base = (uint32_t)__cvta_generic_to_shared(Bs0);
    issue_B(bs_base, cur, tid);

    float rowacc[4] = {0.f, 0.f, 0.f, 0.f};
    float nsum_row[4];
    if (POSPASS) {
#pragma unroll
        for (int k = 0; k < 4; k++) {
            int r = rowBase + wm * 32 + (k >> 1) * 16 + (k & 1) * 8 + g;
            nsum_row[k] = g_neg_sum[r];
        }
    }

    int buf = 0;
    const float C2 = 2.8853900817779268f;  // 2/TEMP * log2(e) with m=2 folded

    for (;;) {
        // find + prefetch next wanted tile
        int nxt = cur + 1;
        while (nxt < jEnd && ((labels[nxt >> 1] == myLab) != POSPASS)) nxt++;
        const bool has_next = (nxt < jEnd);
        if (has_next) issue_B(bs_base + (buf ^ 1) * (BN * KPAD * 2), nxt, tid);

        if (has_next) asm volatile("cp.async.wait_group 1;\n");
        else          asm volatile("cp.async.wait_group 0;\n");
        __syncthreads();

        const __nv_bfloat16* Bs = Bs0 + buf * (BN * KPAD);

        float acc[2][8][4];
#pragma unroll
        for (int mi = 0; mi < 2; mi++)
#pragma unroll
            for (int ni = 0; ni < 8; ni++)
#pragma unroll
                for (int e = 0; e < 4; e++) acc[mi][ni][e] = 0.f;

#pragma unroll 4
        for (int kk = 0; kk < CDIM; kk += 16) {
            uint32_t a[2][4], b[8][2];
#pragma unroll
            for (int mi = 0; mi < 2; mi++) {
                const __nv_bfloat16* ap =
                    &As[(wm * 32 + mi * 16 + g) * KPAD + kk + tig * 2];
                a[mi][0] = *(const uint32_t*)ap;
                a[mi][1] = *(const uint32_t*)(ap + 8 * KPAD);
                a[mi][2] = *(const uint32_t*)(ap + 8);
                a[mi][3] = *(const uint32_t*)(ap + 8 * KPAD + 8);
            }
#pragma unroll
            for (int ni = 0; ni < 8; ni++) {
                const __nv_bfloat16* bp =
                    &Bs[(wn * 64 + ni * 8 + g) * KPAD + kk + tig * 2];
                b[ni][0] = *(const uint32_t*)bp;
                b[ni][1] = *(const uint32_t*)(bp + 8);
            }
#pragma unroll
            for (int mi = 0; mi < 2; mi++)
#pragma unroll
                for (int ni = 0; ni < 8; ni++)
                    mma_bf16(acc[mi][ni], a[mi], b[ni]);
        }

        const int jBase = cur * BN;
#pragma unroll
        for (int mi = 0; mi < 2; mi++) {
#pragma unroll
            for (int h = 0; h < 2; h++) {
                const int ridx = mi * 2 + h;
                float sum = 0.f;
                if (POSPASS) {
                    const int gi = rowBase + wm * 32 + mi * 16 + h * 8 + g;
#pragma unroll
                    for (int ni = 0; ni < 8; ni++) {
#pragma unroll
                        for (int e = 0; e < 2; e++) {
                            float d = acc[mi][ni][h * 2 + e];
                            float l = 2.f * d - 2.f;
                            int gj = jBase + wn * 64 + ni * 8 + tig * 2 + e;
                            if (gi != gj)
                                sum += l - __logf(__expf(l) + nsum_row[ridx]);
                        }
                    }
                } else {
                    // exp(2d-2) = 2^(C2*d - C2), two at a time via ex2.f16x2
#pragma unroll
                    for (int ni = 0; ni < 8; ni++) {
                        float x0 = fmaf(acc[mi][ni][h * 2 + 0], C2, -C2);
                        float x1 = fmaf(acc[mi][ni][h * 2 + 1], C2, -C2);
                        __half2 hx = __floats2half2_rn(x0, x1);
                        uint32_t xu = *reinterpret_cast<uint32_t*>(&hx);
                        uint32_t eu;
                        asm("ex2.approx.f16x2 %0, %1;" : "=r"(eu) : "r"(xu));
                        __half2 he = *reinterpret_cast<__half2*>(&eu);
                        float2 fe = __half22float2(he);
                        sum += fe.x + fe.y;
                    }
                }
                rowacc[ridx] += sum;
            }
        }

        if (!has_next) break;
        __syncthreads();          // all readers done before buf^1's successor
        cur = nxt;
        buf ^= 1;
    }

    // quad-shuffle reduce (lanes sharing a row differ only in tig), then atomic
#pragma unroll
    for (int k = 0; k < 4; k++) {
        float v = rowacc[k];
        v += __shfl_xor_sync(0xffffffffu, v, 1);
        v += __shfl_xor_sync(0xffffffffu, v, 2);
        if (tig == 0) {
            int r = rowBase + wm * 32 + (k >> 1) * 16 + (k & 1) * 8 + g;
            atomicAdd(POSPASS ? &g_pos_sum[r] : &g_neg_sum[r], v);
        }
    }
}

// ---------------------------------------------------------------------------
// K4: loss = -mean_i( pos_sum[i] / (V * same_label_count(t_i) - 1) )
// grid 32 x 256: exactly one row per thread; block partials atomicAdd into out.
// ---------------------------------------------------------------------------
__global__ void k_final(const int* __restrict__ labels, float* __restrict__ out) {
    __shared__ float rcnt[TT];
    __shared__ float wred[8];
    const int tid = threadIdx.x;
    if (tid < TT) {
        int ml = labels[tid], c = 0;
        for (int u = 0; u < TT; u++) c += (labels[u] == ml) ? 1 : 0;
        rcnt[tid] = 1.0f / (float)(c * VV - 1);   // always >= 255 > EPS
    }
    __syncthreads();
    const int i = blockIdx.x * 256 + tid;         // 32*256 == MTOT
    float s = g_pos_sum[i] * rcnt[i >> 8];
#pragma unroll
    for (int off = 16; off > 0; off >>= 1)
        s += __shfl_xor_sync(0xffffffffu, s, off);
    if ((tid & 31) == 0) wred[tid >> 5] = s;
    __syncthreads();
    if (tid == 0) {
        float t = 0.f;
#pragma unroll
        for (int w = 0; w < 8; w++) t += wred[w];
        atomicAdd(out, -t * (1.0f / (float)MTOT));
    }
}

// ---------------------------------------------------------------------------
extern "C" void kernel_launch(void* const* d_in, const int* in_sizes, int n_in,
                              void* d_out, int out_size) {
    const float* features   = (const float*)d_in[0];
    const int*   batch_inds = (const int*)d_in[1];
    const int*   si32       = (const int*)d_in[2];  // int32 or int64 (sniffed)
    const int*   labels     = (const int*)d_in[3];
    float*       out        = (float*)d_out;

    cudaFuncSetAttribute(k_pass<false, 32>,
                         cudaFuncAttributeMaxDynamicSharedMemorySize, SMEM_BYTES);
    cudaFuncSetAttribute(k_pass<true, 16>,
                         cudaFuncAttributeMaxDynamicSharedMemorySize, SMEM_BYTES);

    k_gather<<<dim3(4, TT), 256>>>(features, batch_inds, si32, out);
    k_pass<false, 32><<<dim3(2, 64), 256, SMEM_BYTES>>>(labels);
    k_pass<true, 16><<<dim3(4, 64), 256, SMEM_BYTES>>>(labels);
    k_final<<<32, 256>>>(labels, out);
}

// round 8
// speedup vs baseline: 1.0783x; 1.0002x over previous
#include <cuda_runtime.h>
#include <cuda_bf16.h>
#include <cuda_fp16.h>
#include <cuda_fp8.h>
#include <stdint.h>

#define CDIM 256
#define HW_  9216
#define TT   32
#define VV   256
#define MTOT 8192
#define BM   128
#define BN   128
#define PADB 272                      // 256B row + 16B pad: conflict-free, 16B-aligned
#define TILE_B (BM * PADB)            // 34816 bytes per fp8 tile buffer
#define SMEM_BYTES (3 * TILE_B)       // A + double-buffered B = 102 KB
#define FSCALE 16.0f                  // feature scale (exact pow2); dot scales by 256

__device__ __align__(256) uint8_t g_feats[(size_t)MTOT * CDIM];  // e4m3
__device__ float g_neg_sum[MTOT];
__device__ float g_pos_sum[MTOT];

// ---------------------------------------------------------------------------
// K1: gather + L2 normalize (fp32) -> e4m3 feats (x16); zero accums + out.
// grid (4, 32): blockIdx.y = t, blockIdx.x = quarter of v. 256 thr = (cg, vl).
// ---------------------------------------------------------------------------
__global__ void k_gather(const float* __restrict__ features,
                         const int* __restrict__ batch_inds,
                         const int* __restrict__ si32,
                         float* __restrict__ out) {
    const int tid = threadIdx.x;
    const int t  = blockIdx.y;
    const int vq = blockIdx.x;
    const int vl = tid & 63;
    const int cg = tid >> 6;
    const int v  = vq * 64 + vl;

    if (blockIdx.x == 0 && blockIdx.y == 0 && tid == 0) out[0] = 0.f;
    int gz = ((blockIdx.y * 4 + blockIdx.x) << 8) + tid;
    if (gz < MTOT) { g_neg_sum[gz] = 0.f; g_pos_sum[gz] = 0.f; }

    // sample_inds may arrive as int64 or int32 (JAX x64 flag); sniff high words.
    bool is64 = (si32[1] == 0) && (si32[3] == 0) && (si32[5] == 0) && (si32[7] == 0);
    const int idx = t * VV + v;
    const int s = is64 ? (int)((const long long*)si32)[idx] : si32[idx];
    const int b = batch_inds[t];
    const float* base = features + (size_t)b * CDIM * HW_ + s;

    float partial = 0.f;
#pragma unroll 8
    for (int c = cg * 64; c < cg * 64 + 64; c++) {
        float x = __ldg(&base[(size_t)c * HW_]);
        partial += x * x;
    }
    __shared__ float red[4][64];
    __shared__ float s_inv[64];
    red[cg][vl] = partial;
    __syncthreads();
    if (cg == 0) {
        float ss = red[0][vl] + red[1][vl] + red[2][vl] + red[3][vl];
        s_inv[vl] = 1.0f / fmaxf(sqrtf(ss), 1e-12f);
    }
    __syncthreads();
    const float inv = s_inv[vl] * FSCALE;
    uint8_t* dst = g_feats + (size_t)(t * VV + v) * CDIM;
#pragma unroll 8
    for (int c = cg * 64; c < cg * 64 + 64; c += 2) {
        float x0 = __ldg(&base[(size_t)c * HW_]) * inv;
        float x1 = __ldg(&base[(size_t)(c + 1) * HW_]) * inv;
        __nv_fp8x2_storage_t p = __nv_cvt_float2_to_fp8x2(
            make_float2(x0, x1), __NV_SATFINITE, __NV_E4M3);
        *(unsigned short*)&dst[c] = p;   // low byte = x0
    }
}

// ---------------------------------------------------------------------------
// mma.sync m16n8k32 e4m3 (A row-major, B col-major i.e. [n][k] storage)
// ---------------------------------------------------------------------------
__device__ __forceinline__ void mma_fp8(float c[4], const uint32_t a[4],
                                        const uint32_t b[2]) {
    asm volatile(
        "mma.sync.aligned.m16n8k32.row.col.f32.e4m3.e4m3.f32 "
        "{%0,%1,%2,%3}, {%4,%5,%6,%7}, {%8,%9}, {%0,%1,%2,%3};\n"
        : "+f"(c[0]), "+f"(c[1]), "+f"(c[2]), "+f"(c[3])
        : "r"(a[0]), "r"(a[1]), "r"(a[2]), "r"(a[3]), "r"(b[0]), "r"(b[1]));
}

__device__ __forceinline__ void cp16(uint32_t smem_dst, const void* gsrc) {
    asm volatile("cp.async.cg.shared.global [%0], [%1], 16;\n"
                 :: "r"(smem_dst), "l"(gsrc));
}

// async load of a full 128x256 e4m3 tile (8 cp.async per thread, one group)
__device__ __forceinline__ void issue_B(uint32_t bs_addr, int jt, int tid) {
    const uint4* src = (const uint4*)g_feats + (size_t)jt * BN * (CDIM / 16);
#pragma unroll
    for (int it = 0; it < (BN * CDIM / 16) / 256; it++) {   // 8 iters
        int i = it * 256 + tid;
        int r = i >> 4, cb = i & 15;
        cp16(bs_addr + r * PADB + cb * 16, src + r * 16 + cb);
    }
    asm volatile("cp.async.commit_group;\n");
}

// ---------------------------------------------------------------------------
// K2/K3: one 128-row block x NJT j-tiles per CTA.
// POSPASS=false (grid 2x64): neg_sum[i] = sum_{lab!=} exp(2d-2)   [f16x2 ex2]
// POSPASS=true  (grid 4x64): pos_sum[i] = sum_{lab==, j!=i} [ l - log(e^l + ns_i) ]
// (fixed stabilizer m=2 cancels analytically vs. the reference's row max;
//  raw MMA output = 256 * cosine because features carry a x16 scale)
// ---------------------------------------------------------------------------
template <bool POSPASS, int NJT>
__global__ void k_pass(const int* __restrict__ labels) {
    extern __shared__ uint8_t smem[];
    uint8_t* As  = smem;                      // [BM][PADB]
    uint8_t* Bs0 = smem + TILE_B;             // two [BN][PADB] buffers

    const int rb = blockIdx.y;
    const int jc = blockIdx.x;
    const int rowBase = rb * BM;
    const int myLab = labels[rb >> 1];        // 128 rows lie in one t
    const int tid = threadIdx.x;
    const int lane = tid & 31, warp = tid >> 5;
    const int wm = warp >> 1, wn = warp & 1;  // 4(m) x 2(n) warps
    const int g = lane >> 2, tig = lane & 3;

    const int jEnd = jc * NJT + NJT;
    int cur = jc * NJT;
    while (cur < jEnd && ((labels[cur >> 1] == myLab) != POSPASS)) cur++;
    if (cur >= jEnd) return;

    // load A tile (rows rowBase..+127, full K) into padded shared
    {
        const uint4* src = (const uint4*)g_feats + (size_t)rowBase * (CDIM / 16);
#pragma unroll
        for (int it = 0; it < (BM * CDIM / 16) / 256; it++) {
            int i = it * 256 + tid;
            int r = i >> 4, cb = i & 15;
            *(uint4*)&As[r * PADB + cb * 16] = src[r * 16 + cb];
        }
    }

    uint32_t bs_base;
    asm("{ .reg .u64 t; cvta.to.shared.u64 t, %1; cvt.u32.u64 %0, t; }"
        : "=r"(bs_base) : "l"((void*)Bs0));
    issue_B(bs_base, cur, tid);

    float rowacc[4] = {0.f, 0.f, 0.f, 0.f};
    float nsum_row[4];
    if (POSPASS) {
#pragma unroll
        for (int k = 0; k < 4; k++) {
            int r = rowBase + wm * 32 + (k >> 1) * 16 + (k & 1) * 8 + g;
            nsum_row[k] = g_neg_sum[r];
        }
    }

    int buf = 0;
    // exp(2*cos - 2) = 2^(C2A*draw - C2B), draw = 256*cos
    const float C2A = 0.011270273756944245f;  // 2/TEMP * log2(e) / 256
    const float C2B = 2.8853900817779268f;    // 2/TEMP * log2(e)
    const float RSC = 0.0078125f;             // 1/128: l = draw/128 - 2

    for (;;) {
        int nxt = cur + 1;
        while (nxt < jEnd && ((labels[nxt >> 1] == myLab) != POSPASS)) nxt++;
        const bool has_next = (nxt < jEnd);
        if (has_next) issue_B(bs_base + (buf ^ 1) * TILE_B, nxt, tid);

        if (has_next) asm volatile("cp.async.wait_group 1;\n");
        else          asm volatile("cp.async.wait_group 0;\n");
        __syncthreads();

        const uint8_t* Bs = Bs0 + buf * TILE_B;

        float acc[2][8][4];
#pragma unroll
        for (int mi = 0; mi < 2; mi++)
#pragma unroll
            for (int ni = 0; ni < 8; ni++)
#pragma unroll
                for (int e = 0; e < 4; e++) acc[mi][ni][e] = 0.f;

#pragma unroll
        for (int kk = 0; kk < CDIM; kk += 32) {
            uint32_t a[2][4], b[8][2];
#pragma unroll
            for (int mi = 0; mi < 2; mi++) {
                const uint8_t* ap =
                    &As[(wm * 32 + mi * 16 + g) * PADB + kk + tig * 4];
                a[mi][0] = *(const uint32_t*)ap;
                a[mi][1] = *(const uint32_t*)(ap + 8 * PADB);
                a[mi][2] = *(const uint32_t*)(ap + 16);
                a[mi][3] = *(const uint32_t*)(ap + 8 * PADB + 16);
            }
#pragma unroll
            for (int ni = 0; ni < 8; ni++) {
                const uint8_t* bp =
                    &Bs[(wn * 64 + ni * 8 + g) * PADB + kk + tig * 4];
                b[ni][0] = *(const uint32_t*)bp;
                b[ni][1] = *(const uint32_t*)(bp + 16);
            }
#pragma unroll
            for (int mi = 0; mi < 2; mi++)
#pragma unroll
                for (int ni = 0; ni < 8; ni++)
                    mma_fp8(acc[mi][ni], a[mi], b[ni]);
        }

        const int jBase = cur * BN;
#pragma unroll
        for (int mi = 0; mi < 2; mi++) {
#pragma unroll
            for (int h = 0; h < 2; h++) {
                const int ridx = mi * 2 + h;
                float sum = 0.f;
                if (POSPASS) {
                    const int gi = rowBase + wm * 32 + mi * 16 + h * 8 + g;
#pragma unroll
                    for (int ni = 0; ni < 8; ni++) {
#pragma unroll
                        for (int e = 0; e < 2; e++) {
                            float draw = acc[mi][ni][h * 2 + e];
                            float l = fmaf(draw, RSC, -2.0f);
                            int gj = jBase + wn * 64 + ni * 8 + tig * 2 + e;
                            if (gi != gj)
                                sum += l - __logf(__expf(l) + nsum_row[ridx]);
                        }
                    }
                } else {
#pragma unroll
                    for (int ni = 0; ni < 8; ni++) {
                        float x0 = fmaf(acc[mi][ni][h * 2 + 0], C2A, -C2B);
                        float x1 = fmaf(acc[mi][ni][h * 2 + 1], C2A, -C2B);
                        __half2 hx = __floats2half2_rn(x0, x1);
                        uint32_t xu = *reinterpret_cast<uint32_t*>(&hx), eu;
                        asm("ex2.approx.f16x2 %0, %1;" : "=r"(eu) : "r"(xu));
                        __half2 he = *reinterpret_cast<__half2*>(&eu);
                        float2 fe = __half22float2(he);
                        sum += fe.x + fe.y;
                    }
                }
                rowacc[ridx] += sum;
            }
        }

        if (!has_next) break;
        __syncthreads();          // all readers done before buf^1 reuse
        cur = nxt;
        buf ^= 1;
    }

    // quad-shuffle reduce (lanes sharing a row differ only in tig), then atomic
#pragma unroll
    for (int k = 0; k < 4; k++) {
        float v = rowacc[k];
        v += __shfl_xor_sync(0xffffffffu, v, 1);
        v += __shfl_xor_sync(0xffffffffu, v, 2);
        if (tig == 0) {
            int r = rowBase + wm * 32 + (k >> 1) * 16 + (k & 1) * 8 + g;
            atomicAdd(POSPASS ? &g_pos_sum[r] : &g_neg_sum[r], v);
        }
    }
}

// ---------------------------------------------------------------------------
// K4: loss = -mean_i( pos_sum[i] / (V * same_label_count(t_i) - 1) )
// grid 32 x 256: one row per thread; block partials atomicAdd into out.
// ---------------------------------------------------------------------------
__global__ void k_final(const int* __restrict__ labels, float* __restrict__ out) {
    __shared__ float rcnt[TT];
    __shared__ float wred[8];
    const int tid = threadIdx.x;
    if (tid < TT) {
        int ml = labels[tid], c = 0;
        for (int u = 0; u < TT; u++) c += (labels[u] == ml) ? 1 : 0;
        rcnt[tid] = 1.0f / (float)(c * VV - 1);   // always >= 255 > EPS
    }
    __syncthreads();
    const int i = blockIdx.x * 256 + tid;         // 32*256 == MTOT
    float s = g_pos_sum[i] * rcnt[i >> 8];
#pragma unroll
    for (int off = 16; off > 0; off >>= 1)
        s += __shfl_xor_sync(0xffffffffu, s, off);
    if ((tid & 31) == 0) wred[tid >> 5] = s;
    __syncthreads();
    if (tid == 0) {
        float t = 0.f;
#pragma unroll
        for (int w = 0; w < 8; w++) t += wred[w];
        atomicAdd(out, -t * (1.0f / (float)MTOT));
    }
}

// ---------------------------------------------------------------------------
extern "C" void kernel_launch(void* const* d_in, const int* in_sizes, int n_in,
                              void* d_out, int out_size) {
    const float* features   = (const float*)d_in[0];
    const int*   batch_inds = (const int*)d_in[1];
    const int*   si32       = (const int*)d_in[2];  // int32 or int64 (sniffed)
    const int*   labels     = (const int*)d_in[3];
    float*       out        = (float*)d_out;

    cudaFuncSetAttribute(k_pass<false, 32>,
                         cudaFuncAttributeMaxDynamicSharedMemorySize, SMEM_BYTES);
    cudaFuncSetAttribute(k_pass<true, 16>,
                         cudaFuncAttributeMaxDynamicSharedMemorySize, SMEM_BYTES);

    k_gather<<<dim3(4, TT), 256>>>(features, batch_inds, si32, out);
    k_pass<false, 32><<<dim3(2, 64), 256, SMEM_BYTES>>>(labels);
    k_pass<true, 16><<<dim3(4, 64), 256, SMEM_BYTES>>>(labels);
    k_final<<<32, 256>>>(labels, out);
}

// round 9
// speedup vs baseline: 1.6967x; 1.5734x over previous
#include <cuda_runtime.h>
#include <cuda_bf16.h>
#include <cuda_fp16.h>
#include <cuda_fp8.h>
#include <stdint.h>

#define CDIM 256
#define HW_  9216
#define TT   32
#define VV   256
#define MTOT 8192
#define NB   64                       // 64 row-blocks of 128
#define PADB 272                      // 256B row + 16B pad: conflict-free, 16B-aligned
#define TILE_B (128 * PADB)           // 34816 bytes per fp8 tile buffer
#define SMEM_PAIR (4 * TILE_B)        // double-buffered (A,B) pairs = 136 KB
#define FSCALE 16.0f                  // feature scale (exact pow2); dot scales by 256
#define NPAIRS (NB * (NB + 1) / 2)    // 2080

__device__ __align__(256) uint8_t g_feats[(size_t)MTOT * CDIM];  // e4m3
__device__ float g_neg_sum[MTOT];
__device__ float g_pos_sum[MTOT];
__device__ int g_list_neg[NPAIRS];
__device__ int g_list_pos[NPAIRS];
__device__ int g_cnt_neg, g_cnt_pos;

// ---------------------------------------------------------------------------
// K1: gather + L2 normalize (single read pass, fp32) -> e4m3 feats (x16).
// grid (4, 32): blockIdx.y = t, blockIdx.x = quarter of v. 256 thr = (cg, vl).
// ---------------------------------------------------------------------------
__global__ void __launch_bounds__(256) k_gather(
        const float* __restrict__ features,
        const int* __restrict__ batch_inds,
        const int* __restrict__ si32,
        float* __restrict__ out) {
    const int tid = threadIdx.x;
    const int t  = blockIdx.y;
    const int vq = blockIdx.x;
    const int vl = tid & 63;
    const int cg = tid >> 6;
    const int v  = vq * 64 + vl;

    if (blockIdx.x == 0 && blockIdx.y == 0 && tid == 0) out[0] = 0.f;
    int gz = ((blockIdx.y * 4 + blockIdx.x) << 8) + tid;
    if (gz < MTOT) { g_neg_sum[gz] = 0.f; g_pos_sum[gz] = 0.f; }

    // sample_inds may arrive as int64 or int32 (JAX x64 flag); sniff high words.
    bool is64 = (si32[1] == 0) && (si32[3] == 0) && (si32[5] == 0) && (si32[7] == 0);
    const int idx = t * VV + v;
    const int s = is64 ? (int)((const long long*)si32)[idx] : si32[idx];
    const int b = batch_inds[t];
    const float* base = features + (size_t)b * CDIM * HW_ + (size_t)cg * 64 * HW_ + s;

    float x[64];
#pragma unroll
    for (int i = 0; i < 64; i++) x[i] = __ldg(&base[(size_t)i * HW_]);
    float partial = 0.f;
#pragma unroll
    for (int i = 0; i < 64; i++) partial += x[i] * x[i];

    __shared__ float red[4][64];
    __shared__ float s_inv[64];
    red[cg][vl] = partial;
    __syncthreads();
    if (cg == 0) {
        float ss = red[0][vl] + red[1][vl] + red[2][vl] + red[3][vl];
        s_inv[vl] = 1.0f / fmaxf(sqrtf(ss), 1e-12f);
    }
    __syncthreads();
    const float inv = s_inv[vl] * FSCALE;

    uint32_t w[16];
#pragma unroll
    for (int i = 0; i < 16; i++) {
        __nv_fp8x2_storage_t p0 = __nv_cvt_float2_to_fp8x2(
            make_float2(x[4 * i] * inv, x[4 * i + 1] * inv), __NV_SATFINITE, __NV_E4M3);
        __nv_fp8x2_storage_t p1 = __nv_cvt_float2_to_fp8x2(
            make_float2(x[4 * i + 2] * inv, x[4 * i + 3] * inv), __NV_SATFINITE, __NV_E4M3);
        w[i] = (uint32_t)p0 | ((uint32_t)p1 << 16);
    }
    uint4* dst = (uint4*)(g_feats + (size_t)(t * VV + v) * CDIM + cg * 64);
    dst[0] = make_uint4(w[0], w[1], w[2], w[3]);
    dst[1] = make_uint4(w[4], w[5], w[6], w[7]);
    dst[2] = make_uint4(w[8], w[9], w[10], w[11]);
    dst[3] = make_uint4(w[12], w[13], w[14], w[15]);
}

// ---------------------------------------------------------------------------
// K2: build symmetric block-pair worklists (I<=J), deterministic order.
// neg: lab[I]!=lab[J] (never diagonal). pos: lab equal (incl. diagonal).
// ---------------------------------------------------------------------------
__global__ void k_lists(const int* __restrict__ labels) {
    __shared__ int cN[NB], cP[NB];
    const int I = threadIdx.x;                   // 64 threads
    const int lI = labels[I >> 1];
    int nN = 0, nP = 0;
    for (int J = I; J < NB; J++) {
        if (labels[J >> 1] == lI) nP++; else nN++;
    }
    cN[I] = nN; cP[I] = nP;
    __syncthreads();
    int oN = 0, oP = 0;
    for (int k = 0; k < I; k++) { oN += cN[k]; oP += cP[k]; }
    for (int J = I; J < NB; J++) {
        int ent = (I << 8) | J;
        if (labels[J >> 1] == lI) g_list_pos[oP++] = ent;
        else                      g_list_neg[oN++] = ent;
    }
    if (I == NB - 1) { g_cnt_neg = oN; g_cnt_pos = oP; }
}

// ---------------------------------------------------------------------------
// mma.sync m16n8k32 e4m3 (A row-major, B col-major i.e. [n][k] storage)
// ---------------------------------------------------------------------------
__device__ __forceinline__ void mma_fp8(float c[4], const uint32_t a[4],
                                        const uint32_t b[2]) {
    asm volatile(
        "mma.sync.aligned.m16n8k32.row.col.f32.e4m3.e4m3.f32 "
        "{%0,%1,%2,%3}, {%4,%5,%6,%7}, {%8,%9}, {%0,%1,%2,%3};\n"
        : "+f"(c[0]), "+f"(c[1]), "+f"(c[2]), "+f"(c[3])
        : "r"(a[0]), "r"(a[1]), "r"(a[2]), "r"(a[3]), "r"(b[0]), "r"(b[1]));
}

__device__ __forceinline__ void cp16(uint32_t smem_dst, const void* gsrc) {
    asm volatile("cp.async.cg.shared.global [%0], [%1], 16;\n"
                 :: "r"(smem_dst), "l"(gsrc));
}

// async load of a full 128x256 e4m3 tile (8 cp.async per thread)
__device__ __forceinline__ void load_tile(uint32_t dst, int row0, int tid) {
    const uint4* src = (const uint4*)g_feats + (size_t)row0 * (CDIM / 16);
#pragma unroll
    for (int it = 0; it < 8; it++) {
        int i = it * 256 + tid;
        int r = i >> 4, cb = i & 15;
        cp16(dst + r * PADB + cb * 16, src + r * 16 + cb);
    }
}

// ---------------------------------------------------------------------------
// K3/K4: symmetric block-pair pass. Each pair (I,J), I<=J, computed ONCE;
// contributions scattered to rows of I (row sums) AND rows of J (col sums).
// POSPASS=false: e = exp(2cos-2); neg_sum[i] += e, neg_sum[j] += e.
// POSPASS=true : pos_sum[i] += l - log(e^l + ns_i); (off-diag also for j).
// Raw MMA output = 256*cos (features carry x16); m=2 stabilizer cancels.
// ---------------------------------------------------------------------------
template <bool POSPASS>
__global__ void __launch_bounds__(256) k_pair(const int* __restrict__ labels) {
    extern __shared__ uint8_t smem[];
    const int cnt = POSPASS ? g_cnt_pos : g_cnt_neg;
    const int* list = POSPASS ? g_list_pos : g_list_neg;
    const int G = gridDim.x;
    if ((int)blockIdx.x >= cnt) return;

    const int tid = threadIdx.x;
    const int lane = tid & 31, warp = tid >> 5;
    const int wm = warp >> 1, wn = warp & 1;     // 4(m) x 2(n) warps
    const int g = lane >> 2, tig = lane & 3;

    uint32_t sbase;
    asm("{ .reg .u64 t; cvta.to.shared.u64 t, %1; cvt.u32.u64 %0, t; }"
        : "=r"(sbase) : "l"((void*)smem));

    // prologue: pair p into slot0, pair p+G into slot1 (commit each, maybe empty)
    {
        int ent = list[blockIdx.x];
        load_tile(sbase, (ent >> 8) * 128, tid);
        load_tile(sbase + TILE_B, (ent & 255) * 128, tid);
    }
    asm volatile("cp.async.commit_group;\n");
    if ((int)blockIdx.x + G < cnt) {
        int ent = list[blockIdx.x + G];
        load_tile(sbase + 2 * TILE_B, (ent >> 8) * 128, tid);
        load_tile(sbase + 3 * TILE_B, (ent & 255) * 128, tid);
    }
    asm volatile("cp.async.commit_group;\n");

    const float C2A = 0.011270273756944245f;  // 2/TEMP*log2(e)/256
    const float C2B = 2.8853900817779268f;    // 2/TEMP*log2(e)
    const float RSC = 0.0078125f;             // 1/128: l = draw/128 - 2

    int s = 0;
    for (int p = blockIdx.x; p < cnt; p += G, s ^= 1) {
        const int ent = list[p];
        const int I = ent >> 8, J = ent & 255;
        const bool diag = (I == J);

        asm volatile("cp.async.wait_group 1;\n");
        __syncthreads();

        const uint8_t* As = smem + s * 2 * TILE_B;
        const uint8_t* Bs = As + TILE_B;

        float acc[2][8][4];
#pragma unroll
        for (int mi = 0; mi < 2; mi++)
#pragma unroll
            for (int ni = 0; ni < 8; ni++)
#pragma unroll
                for (int e = 0; e < 4; e++) acc[mi][ni][e] = 0.f;

#pragma unroll
        for (int kk = 0; kk < CDIM; kk += 32) {
            uint32_t a[2][4], b[8][2];
#pragma unroll
            for (int mi = 0; mi < 2; mi++) {
                const uint8_t* ap = &As[(wm * 32 + mi * 16 + g) * PADB + kk + tig * 4];
                a[mi][0] = *(const uint32_t*)ap;
                a[mi][1] = *(const uint32_t*)(ap + 8 * PADB);
                a[mi][2] = *(const uint32_t*)(ap + 16);
                a[mi][3] = *(const uint32_t*)(ap + 8 * PADB + 16);
            }
#pragma unroll
            for (int ni = 0; ni < 8; ni++) {
                const uint8_t* bp = &Bs[(wn * 64 + ni * 8 + g) * PADB + kk + tig * 4];
                b[ni][0] = *(const uint32_t*)bp;
                b[ni][1] = *(const uint32_t*)(bp + 16);
            }
#pragma unroll
            for (int mi = 0; mi < 2; mi++)
#pragma unroll
                for (int ni = 0; ni < 8; ni++)
                    mma_fp8(acc[mi][ni], a[mi], b[ni]);
        }

        // ------------------ epilogue: scatter rows (I) + cols (J) ----------
        float colp[16];
#pragma unroll
        for (int k = 0; k < 16; k++) colp[k] = 0.f;

        float nsr[4], nsc[16];
        if (POSPASS) {
#pragma unroll
            for (int k = 0; k < 4; k++)
                nsr[k] = g_neg_sum[I * 128 + wm * 32 + (k >> 1) * 16 + (k & 1) * 8 + g];
            if (!diag) {
#pragma unroll
                for (int k = 0; k < 16; k++)
                    nsc[k] = g_neg_sum[J * 128 + wn * 64 + (k >> 1) * 8 + tig * 2 + (k & 1)];
            }
        }

#pragma unroll
        for (int mi = 0; mi < 2; mi++) {
#pragma unroll
            for (int h = 0; h < 2; h++) {
                const int ridx = mi * 2 + h;
                const int gi = I * 128 + wm * 32 + mi * 16 + h * 8 + g;
                float rsum = 0.f;
                if (POSPASS) {
#pragma unroll
                    for (int ni = 0; ni < 8; ni++) {
#pragma unroll
                        for (int e = 0; e < 2; e++) {
                            float l = fmaf(acc[mi][ni][h * 2 + e], RSC, -2.0f);
                            int gj = J * 128 + wn * 64 + ni * 8 + tig * 2 + e;
                            float el = __expf(l);
                            if (!diag || gi != gj)
                                rsum += l - __logf(el + nsr[ridx]);
                            if (!diag)
                                colp[ni * 2 + e] += l - __logf(el + nsc[ni * 2 + e]);
                        }
                    }
                } else {
#pragma unroll
                    for (int ni = 0; ni < 8; ni++) {
                        float x0 = fmaf(acc[mi][ni][h * 2 + 0], C2A, -C2B);
                        float x1 = fmaf(acc[mi][ni][h * 2 + 1], C2A, -C2B);
                        __half2 hx = __floats2half2_rn(x0, x1);
                        uint32_t xu = *reinterpret_cast<uint32_t*>(&hx), eu;
                        asm("ex2.approx.f16x2 %0, %1;" : "=r"(eu) : "r"(xu));
                        __half2 he = *reinterpret_cast<__half2*>(&eu);
                        float2 fe = __half22float2(he);
                        rsum += fe.x + fe.y;
                        colp[ni * 2 + 0] += fe.x;
                        colp[ni * 2 + 1] += fe.y;
                    }
                }
                rsum += __shfl_xor_sync(0xffffffffu, rsum, 1);
                rsum += __shfl_xor_sync(0xffffffffu, rsum, 2);
                if (tig == 0)
                    atomicAdd(POSPASS ? &g_pos_sum[gi] : &g_neg_sum[gi], rsum);
            }
        }

        if (!POSPASS || !diag) {
#pragma unroll
            for (int k = 0; k < 16; k++) {
                float v = colp[k];
                v += __shfl_xor_sync(0xffffffffu, v, 4);
                v += __shfl_xor_sync(0xffffffffu, v, 8);
                v += __shfl_xor_sync(0xffffffffu, v, 16);
                if (lane < 4) {
                    int gj = J * 128 + wn * 64 + (k >> 1) * 8 + lane * 2 + (k & 1);
                    atomicAdd(POSPASS ? &g_pos_sum[gj] : &g_neg_sum[gj], v);
                }
            }
        }

        __syncthreads();                         // done reading slot s
        if (p + 2 * G < cnt) {                   // prefetch pair p+2G into slot s
            int en = list[p + 2 * G];
            load_tile(sbase + s * 2 * TILE_B, (en >> 8) * 128, tid);
            load_tile(sbase + s * 2 * TILE_B + TILE_B, (en & 255) * 128, tid);
        }
        asm volatile("cp.async.commit_group;\n");
    }
}

// ---------------------------------------------------------------------------
// K5: loss = -mean_i( pos_sum[i] / (V * same_label_count(t_i) - 1) )
// ---------------------------------------------------------------------------
__global__ void k_final(const int* __restrict__ labels, float* __restrict__ out) {
    __shared__ float rcnt[TT];
    __shared__ float wred[8];
    const int tid = threadIdx.x;
    if (tid < TT) {
        int ml = labels[tid], c = 0;
        for (int u = 0; u < TT; u++) c += (labels[u] == ml) ? 1 : 0;
        rcnt[tid] = 1.0f / (float)(c * VV - 1);   // always >= 255 > EPS
    }
    __syncthreads();
    const int i = blockIdx.x * 256 + tid;         // 32*256 == MTOT
    float s = g_pos_sum[i] * rcnt[i >> 8];
#pragma unroll
    for (int off = 16; off > 0; off >>= 1)
        s += __shfl_xor_sync(0xffffffffu, s, off);
    if ((tid & 31) == 0) wred[tid >> 5] = s;
    __syncthreads();
    if (tid == 0) {
        float t = 0.f;
#pragma unroll
        for (int w = 0; w < 8; w++) t += wred[w];
        atomicAdd(out, -t * (1.0f / (float)MTOT));
    }
}

// ---------------------------------------------------------------------------
extern "C" void kernel_launch(void* const* d_in, const int* in_sizes, int n_in,
                              void* d_out, int out_size) {
    const float* features   = (const float*)d_in[0];
    const int*   batch_inds = (const int*)d_in[1];
    const int*   si32       = (const int*)d_in[2];  // int32 or int64 (sniffed)
    const int*   labels     = (const int*)d_in[3];
    float*       out        = (float*)d_out;

    cudaFuncSetAttribute(k_pair<false>,
                         cudaFuncAttributeMaxDynamicSharedMemorySize, SMEM_PAIR);
    cudaFuncSetAttribute(k_pair<true>,
                         cudaFuncAttributeMaxDynamicSharedMemorySize, SMEM_PAIR);

    k_gather<<<dim3(4, TT), 256>>>(features, batch_inds, si32, out);
    k_lists<<<1, NB>>>(labels);
    k_pair<false><<<152, 256, SMEM_PAIR>>>(labels);
    k_pair<true ><<<152, 256, SMEM_PAIR>>>(labels);
    k_final<<<32, 256>>>(labels, out);
}